// round 4
// baseline (speedup 1.0000x reference)
#include <cuda_runtime.h>

#define BB    64
#define CC    256
#define DDIM  256
#define HW    784
#define ATTRN 300
#define O1    32

typedef unsigned long long ull_t;

// scratch (device globals — no allocation allowed)
__device__ float g_emb[BB * CC];           // s1-scaled embedding
__device__ float g_CM[BB * O1 * DDIM];     // per-batch folded conv1 x circulant

// ---- packed f32x2 helpers -------------------------------------------------
__device__ __forceinline__ ull_t fma2(ull_t a, ull_t b, ull_t c) {
    ull_t d;
    asm("fma.rn.f32x2 %0, %1, %2, %3;" : "=l"(d) : "l"(a), "l"(b), "l"(c));
    return d;
}
__device__ __forceinline__ float2 unpk2(ull_t v) {
    float2 r;
    asm("mov.b64 {%0, %1}, %2;" : "=f"(r.x), "=f"(r.y) : "l"(v));
    return r;
}

// ---------------------------------------------------------------------------
// Kernel 1: g_emb[b,c] = s1[c] * (W_emb[c]·attr[b] + b_emb[c])
// Thread-per-(b,c). attr fully staged, padded stride 301 (conflict-free).
// W rows staged; warp-uniform broadcast reads. No shfl chains.
// grid = 64 blocks (4 channels each) x 256 threads (64 b x 4 c)
// ---------------------------------------------------------------------------
#define K1_ASTR 301
__global__ void __launch_bounds__(256) k1_emb(
    const float* __restrict__ attr_oh,   // [B, ATTR]
    const float* __restrict__ W_emb,     // [C, ATTR]
    const float* __restrict__ b_emb,
    const float* __restrict__ s1)
{
    extern __shared__ float sh1[];
    float* attr_s = sh1;                  // [64 * 301]
    float* Ws     = sh1 + BB * K1_ASTR;   // [4 * 300]

    int tid = threadIdx.x;
    int c0  = blockIdx.x * 4;

    for (int i = tid; i < BB * ATTRN; i += 256) {
        int bb = i / ATTRN;
        int aa = i - bb * ATTRN;
        attr_s[bb * K1_ASTR + aa] = attr_oh[i];
    }
    for (int i = tid; i < 4 * ATTRN; i += 256) {
        int ci = i / ATTRN;
        int aa = i - ci * ATTRN;
        Ws[ci * ATTRN + aa] = W_emb[(c0 + ci) * ATTRN + aa];
    }
    __syncthreads();

    int b  = tid & 63;
    int ci = tid >> 6;          // warp-uniform
    const float* wr = Ws + ci * ATTRN;
    const float* ar = attr_s + b * K1_ASTR;

    float a0 = 0.f, a1 = 0.f, a2 = 0.f, a3 = 0.f;
#pragma unroll 5
    for (int a = 0; a < ATTRN; a += 4) {
        a0 = fmaf(wr[a + 0], ar[a + 0], a0);
        a1 = fmaf(wr[a + 1], ar[a + 1], a1);
        a2 = fmaf(wr[a + 2], ar[a + 2], a2);
        a3 = fmaf(wr[a + 3], ar[a + 3], a3);
    }
    int c = c0 + ci;
    g_emb[b * CC + c] = s1[c] * ((a0 + a1) + (a2 + a3) + b_emb[c]);
}

// ---------------------------------------------------------------------------
// Kernel 2: CM[b,o,m] = sum_j conv1_w[o,(m+j)&255] * sa[b,j]
// Doubled dup table wd2[o][512] (float2) kills the &255 and address IMADs:
// inner loads are [base + imm]. Batch pairs in f32x2 lanes, 4 batches/block.
// grid = (8 m-tiles, 16 batch-groups), 256 threads, 132 KB smem
// ---------------------------------------------------------------------------
__global__ void __launch_bounds__(256) k2_cm(
    const float* __restrict__ conv1_w,   // [32,256]
    const int*   __restrict__ h1)        // [256]
{
    extern __shared__ char sm2[];
    float2* wd2  = (float2*)sm2;                        // [32][512] dup, 128KB
    float2* sasp = (float2*)(sm2 + O1 * 512 * 8);       // [2][256]
    int tid = threadIdx.x;
    int b0  = blockIdx.y * 4;

    // stage conv1_w duplicated + doubled (scalar loads, stride-2-word STS)
    for (int i = tid; i < O1 * DDIM; i += 256) {
        int o = i >> 8, k = i & 255;
        float v = conv1_w[i];
        float2 vv = make_float2(v, v);
        wd2[o * 512 + k]       = vv;
        wd2[o * 512 + 256 + k] = vv;
    }
    for (int i = tid; i < 2 * DDIM; i += 256) sasp[i] = make_float2(0.f, 0.f);
    __syncthreads();

    int hv = h1[tid];
#pragma unroll
    for (int p = 0; p < 2; p++) {
        float vx = g_emb[(b0 + 2 * p)     * CC + tid];
        float vy = g_emb[(b0 + 2 * p + 1) * CC + tid];
        atomicAdd(&sasp[p * DDIM + hv].x, vx);
        atomicAdd(&sasp[p * DDIM + hv].y, vy);
    }
    __syncthreads();

    int m  = blockIdx.x * 32 + (tid & 31);
    int o0 = (tid >> 5) << 2;
    const ull_t* wbase = (const ull_t*)wd2 + o0 * 512 + m;
    const ull_t* sp    = (const ull_t*)sasp;

    ull_t acc[2][4];
#pragma unroll
    for (int p = 0; p < 2; p++)
#pragma unroll
        for (int oo = 0; oo < 4; oo++) acc[p][oo] = 0ull;

#pragma unroll 8
    for (int j = 0; j < DDIM; j++) {
        ull_t s0 = sp[j], s1v = sp[DDIM + j];
#pragma unroll
        for (int oo = 0; oo < 4; oo++) {
            ull_t wv = wbase[oo * 512 + j];
            acc[0][oo] = fma2(wv, s0,  acc[0][oo]);
            acc[1][oo] = fma2(wv, s1v, acc[1][oo]);
        }
    }

#pragma unroll
    for (int p = 0; p < 2; p++)
#pragma unroll
        for (int oo = 0; oo < 4; oo++) {
            float2 f = unpk2(acc[p][oo]);
            g_CM[((b0 + 2 * p)     * O1 + o0 + oo) * DDIM + m] = f.x;
            g_CM[((b0 + 2 * p + 1) * O1 + o0 + oo) * DDIM + m] = f.y;
        }
}

// ---------------------------------------------------------------------------
// Kernel 3: fused GEMM (FFMA2) + sigmoid gate + broadcast multiply
// CM staged transposed in smem -> h2 gather from LDS (no L1 replay storm).
// A stored as dup float2, c-stride 34 ull -> aligned LDS.128 feeds 2 o's.
// grid = (7 tiles, 64 batches), 224 threads (28 quads x 8 o-groups), ~105KB
// ---------------------------------------------------------------------------
#define A_CSTR 34    // ull (=float2) per c-row: 32 o + 2 pad, 16B-aligned rows
__global__ void __launch_bounds__(224) k3_main(
    const float* __restrict__ x,        // [B, C, HW]
    const int*   __restrict__ h2,
    const float* __restrict__ s2,
    const float* __restrict__ conv2_w,  // [32]
    float* __restrict__ out_map,        // [B, HW]
    float* __restrict__ out_feat)       // [B, C, HW]
{
    extern __shared__ char sm3[];
    float2* A2    = (float2*)sm3;                             // [256*34] 69,632B
    float*  CMt   = (float*)(sm3 + CC * A_CSTR * 8);          // [256*33] 33,792B
    float4* red4  = (float4*)((char*)CMt + DDIM * 33 * 4);    // [224]
    float4* marr4 = (float4*)((char*)red4 + 224 * 16);        // [28]
    float*  w2s   = (float*)((char*)marr4 + 28 * 16);         // [32]

    int b    = blockIdx.y;
    int tile = blockIdx.x;
    int tid  = threadIdx.x;
    int og   = tid & 7;        // o-group (4 o's)
    int ql   = tid >> 3;       // quad 0..27

    // stage CM transposed: CMt[m][o], coalesced global reads
    const float* cmb = g_CM + b * O1 * DDIM;
    for (int i = tid; i < O1 * DDIM; i += 224) {
        int o = i >> 8, m = i & 255;
        CMt[m * 33 + o] = cmb[i];
    }
    if (tid < O1) w2s[tid] = conv2_w[tid];
    __syncthreads();

    // gather by h2 from shared (lanes sweep o: conflict-free), write dup pairs
    for (int i = tid; i < CC * O1; i += 224) {
        int c = i >> 5, o = i & 31;          // c warp-uniform (224 % 32 == 0)
        float v = s2[c] * CMt[h2[c] * 33 + o];
        A2[c * A_CSTR + o] = make_float2(v, v);
    }
    __syncthreads();

    int p = (tile * 28 + ql) * 4;            // 196 quads exactly
    const float* xb = x + (size_t)b * CC * HW;
    const ull_t* Au = (const ull_t*)A2;

    ull_t acc[4][2];
#pragma unroll
    for (int oo = 0; oo < 4; oo++) { acc[oo][0] = 0ull; acc[oo][1] = 0ull; }

#pragma unroll 4
    for (int c = 0; c < CC; c++) {
        ulonglong2 xv = *(const ulonglong2*)(xb + (size_t)c * HW + p);
        const ulonglong2* ap2 = (const ulonglong2*)(Au + c * A_CSTR + og * 4);
        ulonglong2 apA = ap2[0];   // dup(a[og*4+0]), dup(a[og*4+1])
        ulonglong2 apB = ap2[1];   // dup(a[og*4+2]), dup(a[og*4+3])
        acc[0][0] = fma2(apA.x, xv.x, acc[0][0]);
        acc[0][1] = fma2(apA.x, xv.y, acc[0][1]);
        acc[1][0] = fma2(apA.y, xv.x, acc[1][0]);
        acc[1][1] = fma2(apA.y, xv.y, acc[1][1]);
        acc[2][0] = fma2(apB.x, xv.x, acc[2][0]);
        acc[2][1] = fma2(apB.x, xv.y, acc[2][1]);
        acc[3][0] = fma2(apB.y, xv.x, acc[3][0]);
        acc[3][1] = fma2(apB.y, xv.y, acc[3][1]);
    }

    // relu + conv2 partial over this thread's 4 o's
    float4 ps = make_float4(0.f, 0.f, 0.f, 0.f);
#pragma unroll
    for (int oo = 0; oo < 4; oo++) {
        float w = w2s[og * 4 + oo];
        float2 lo = unpk2(acc[oo][0]);
        float2 hi = unpk2(acc[oo][1]);
        ps.x = fmaf(w, fmaxf(lo.x, 0.f), ps.x);
        ps.y = fmaf(w, fmaxf(lo.y, 0.f), ps.y);
        ps.z = fmaf(w, fmaxf(hi.x, 0.f), ps.z);
        ps.w = fmaf(w, fmaxf(hi.y, 0.f), ps.w);
    }
    red4[tid] = ps;
    __syncthreads();

    if (tid < 28) {
        float4 t = make_float4(0.f, 0.f, 0.f, 0.f);
#pragma unroll
        for (int g = 0; g < 8; g++) {
            float4 r = red4[tid * 8 + g];
            t.x += r.x; t.y += r.y; t.z += r.z; t.w += r.w;
        }
        float4 mm;
        mm.x = 1.f / (1.f + __expf(-t.x));
        mm.y = 1.f / (1.f + __expf(-t.y));
        mm.z = 1.f / (1.f + __expf(-t.z));
        mm.w = 1.f / (1.f + __expf(-t.w));
        marr4[tid] = mm;
        *(float4*)(out_map + b * HW + (tile * 28 + tid) * 4) = mm;
    }
    __syncthreads();

    // epilogue: feat = map * x (x re-read is L1/L2-hot). No divides in loop.
    {
        int qq = tid % 28;
        int cg = tid / 28;                 // 0..7
        int pp = (tile * 28 + qq) * 4;
        float4 mm = marr4[qq];
        float* fb = out_feat + (size_t)b * CC * HW;
        for (int c = cg; c < CC; c += 8) {
            float4 xv = *(const float4*)(xb + (size_t)c * HW + pp);
            float4 r;
            r.x = mm.x * xv.x; r.y = mm.y * xv.y;
            r.z = mm.z * xv.z; r.w = mm.w * xv.w;
            *(float4*)(fb + (size_t)c * HW + pp) = r;
        }
    }
}

// ---------------------------------------------------------------------------
extern "C" void kernel_launch(void* const* d_in, const int* in_sizes, int n_in,
                              void* d_out, int out_size)
{
    (void)in_sizes; (void)n_in; (void)out_size;
    const float* x        = (const float*)d_in[0];
    const float* attr_oh  = (const float*)d_in[1];
    const float* W_emb    = (const float*)d_in[2];
    const float* b_emb    = (const float*)d_in[3];
    const int*   h1       = (const int*)  d_in[4];
    const float* s1       = (const float*)d_in[5];
    const int*   h2       = (const int*)  d_in[6];
    const float* s2       = (const float*)d_in[7];
    const float* conv1_w  = (const float*)d_in[8];
    const float* conv2_w  = (const float*)d_in[9];

    float* out      = (float*)d_out;
    float* out_map  = out;               // [64,784]
    float* out_feat = out + BB * HW;     // [64,256,784]

    const int sh1 = (BB * K1_ASTR + 4 * ATTRN) * 4;                 // ~82 KB
    const int sh2 = O1 * 512 * 8 + 2 * DDIM * 8;                    // ~132 KB
    const int sh3 = CC * A_CSTR * 8 + DDIM * 33 * 4
                  + 224 * 16 + 28 * 16 + O1 * 4;                    // ~106 KB
    cudaFuncSetAttribute(k1_emb,  cudaFuncAttributeMaxDynamicSharedMemorySize, sh1);
    cudaFuncSetAttribute(k2_cm,   cudaFuncAttributeMaxDynamicSharedMemorySize, sh2);
    cudaFuncSetAttribute(k3_main, cudaFuncAttributeMaxDynamicSharedMemorySize, sh3);

    k1_emb<<<64, 256, sh1>>>(attr_oh, W_emb, b_emb, s1);
    k2_cm<<<dim3(8, 16), 256, sh2>>>(conv1_w, h1);
    k3_main<<<dim3(7, BB), 224, sh3>>>(x, h2, s2, conv2_w, out_map, out_feat);
}

// round 7
// speedup vs baseline: 1.3621x; 1.3621x over previous
#include <cuda_runtime.h>

#define BB    64
#define CC    256
#define DDIM  256
#define HW    784
#define ATTRN 300
#define O1    32
#define A_CSTR 34   // float2 per c-row of g_A / A2: 32 o + 2 pad

typedef unsigned long long ull_t;

// scratch (device globals — no allocation allowed)
__device__ float  g_emb[BB * CC];            // s1-scaled embedding
__device__ float  g_CM[BB * O1 * DDIM];      // folded conv1 x circulant
__device__ float2 g_A[BB * CC * A_CSTR];     // dup-pair A matrix per batch

// ---- packed f32x2 helpers -------------------------------------------------
__device__ __forceinline__ ull_t fma2(ull_t a, ull_t b, ull_t c) {
    ull_t d;
    asm("fma.rn.f32x2 %0, %1, %2, %3;" : "=l"(d) : "l"(a), "l"(b), "l"(c));
    return d;
}
__device__ __forceinline__ float2 unpk2(ull_t v) {
    float2 r;
    asm("mov.b64 {%0, %1}, %2;" : "=f"(r.x), "=f"(r.y) : "l"(v));
    return r;
}

// ---------------------------------------------------------------------------
// Kernel 1: g_emb[b,c] = s1[c] * (W_emb[c]·attr[b] + b_emb[c])
// attr staged in NATIVE layout (pure float4 memcpy). Dot via f32x2 over
// ulonglong2: 75 x (2 LDS.128 + 2 FFMA2) per thread.
// grid = 64 blocks (4 channels) x 256 threads (64 b x 4 c)
// ---------------------------------------------------------------------------
__global__ void __launch_bounds__(256) k1_emb(
    const float* __restrict__ attr_oh,   // [B, ATTR]
    const float* __restrict__ W_emb,     // [C, ATTR]
    const float* __restrict__ b_emb,
    const float* __restrict__ s1)
{
    extern __shared__ float sh1[];
    float* attr_s = sh1;                  // [64*300] native layout
    float* Ws     = sh1 + BB * ATTRN;     // [4*300]
    int tid = threadIdx.x;
    int c0  = blockIdx.x * 4;

    {   // pure float4 memcpy staging
        const float4* src = (const float4*)attr_oh;
        float4* dst = (float4*)attr_s;
        for (int i = tid; i < BB * (ATTRN / 4); i += 256) dst[i] = src[i];
        const float4* wsrc = (const float4*)(W_emb + (size_t)c0 * ATTRN);
        float4* wdst = (float4*)Ws;
        for (int i = tid; i < 4 * (ATTRN / 4); i += 256) wdst[i] = wsrc[i];
    }
    __syncthreads();

    int b = tid & 63, ci = tid >> 6;      // ci warp-uniform
    const ulonglong2* ar = (const ulonglong2*)(attr_s + b * ATTRN);
    const ulonglong2* wr = (const ulonglong2*)(Ws + ci * ATTRN);

    ull_t acc0 = 0ull, acc1 = 0ull;
#pragma unroll 15
    for (int k = 0; k < ATTRN / 4; k++) {  // 75 ulonglong2 = 300 floats
        ulonglong2 av = ar[k];
        ulonglong2 wv = wr[k];             // broadcast
        acc0 = fma2(wv.x, av.x, acc0);
        acc1 = fma2(wv.y, av.y, acc1);
    }
    float2 f0 = unpk2(acc0), f1 = unpk2(acc1);
    int c = c0 + ci;
    g_emb[b * CC + c] = s1[c] * ((f0.x + f0.y) + (f1.x + f1.y) + b_emb[c]);
}

// ---------------------------------------------------------------------------
// Kernel 2: CM[b,o,m] = sum_j conv1_w[o,(m+j)&255] * sa[b,j]
// conv1_w dup-pair table (64KB), sketch built via shared atomics, batch
// pairs in f32x2 lanes. grid = (8 m-tiles, 16 batch-groups), 256 threads.
// ---------------------------------------------------------------------------
__global__ void __launch_bounds__(256) k2_cm(
    const float* __restrict__ conv1_w,   // [32,256]
    const int*   __restrict__ h1)        // [256]
{
    extern __shared__ char sm2[];
    float2* wd   = (float2*)sm2;                    // [32*256] dup, 64KB
    float2* sasp = (float2*)(sm2 + O1 * DDIM * 8);  // [2*256]
    int tid = threadIdx.x;
    int b0  = blockIdx.y * 4;

    for (int i = tid; i < O1 * DDIM; i += 256) {
        float v = conv1_w[i];
        wd[i] = make_float2(v, v);
    }
    for (int i = tid; i < 2 * DDIM; i += 256) sasp[i] = make_float2(0.f, 0.f);
    __syncthreads();

    int hv = h1[tid];
#pragma unroll
    for (int p = 0; p < 2; p++) {
        float vx = g_emb[(b0 + 2 * p)     * CC + tid];
        float vy = g_emb[(b0 + 2 * p + 1) * CC + tid];
        atomicAdd(&sasp[p * DDIM + hv].x, vx);
        atomicAdd(&sasp[p * DDIM + hv].y, vy);
    }
    __syncthreads();

    int ml = tid & 31;
    int m0 = blockIdx.x * 32;
    int o0 = (tid >> 5) << 2;
    const ull_t* wdu = (const ull_t*)wd + o0 * DDIM;
    const ull_t* sp  = (const ull_t*)sasp;

    ull_t acc[2][4];
#pragma unroll
    for (int p = 0; p < 2; p++)
#pragma unroll
        for (int oo = 0; oo < 4; oo++) acc[p][oo] = 0ull;

#pragma unroll 8
    for (int j = 0; j < DDIM; j++) {
        int idx = (m0 + ml + j) & (DDIM - 1);
        ull_t s0 = sp[j], s1v = sp[DDIM + j];
#pragma unroll
        for (int oo = 0; oo < 4; oo++) {
            ull_t wv = wdu[oo * DDIM + idx];
            acc[0][oo] = fma2(wv, s0,  acc[0][oo]);
            acc[1][oo] = fma2(wv, s1v, acc[1][oo]);
        }
    }

    int m = m0 + ml;
#pragma unroll
    for (int p = 0; p < 2; p++)
#pragma unroll
        for (int oo = 0; oo < 4; oo++) {
            float2 f = unpk2(acc[p][oo]);
            g_CM[((b0 + 2 * p)     * O1 + o0 + oo) * DDIM + m] = f.x;
            g_CM[((b0 + 2 * p + 1) * O1 + o0 + oo) * DDIM + m] = f.y;
        }
}

// ---------------------------------------------------------------------------
// Kernel 2b: h2 gather done ONCE per batch:
//   g_A[b][c][o] = dup( s2[c] * CM[b][o][h2[c]] )
// grid = 64 (b) x 256 threads. All accesses coalesced / conflict-free.
// ---------------------------------------------------------------------------
__global__ void __launch_bounds__(256) k2b_gather(
    const int*   __restrict__ h2,
    const float* __restrict__ s2)
{
    extern __shared__ float sm2b[];       // CMs[o*257+m], ~33KB
    int b = blockIdx.x;
    int tid = threadIdx.x;

    const float* cmb = g_CM + b * O1 * DDIM;
    for (int i = tid; i < O1 * DDIM; i += 256) {
        int o = i >> 8, m = i & 255;
        sm2b[o * 257 + m] = cmb[i];       // coalesced LDG
    }
    __syncthreads();

    float2* Ab = g_A + (size_t)b * CC * A_CSTR;
    for (int i = tid; i < CC * O1; i += 256) {
        int o = i & 31, c = i >> 5;       // c warp-uniform, lanes sweep o
        float v = s2[c] * sm2b[o * 257 + h2[c]];   // stride 257: conflict-free
        Ab[c * A_CSTR + o] = make_float2(v, v);    // coalesced STG.64
    }
}

// ---------------------------------------------------------------------------
// Kernel 3: fused GEMM (FFMA2) + sigmoid gate + broadcast multiply
// A2 is a straight copy of g_A[b] (no gather/transpose in-kernel).
// grid = (7 tiles, 64 batches), 224 threads (28 quads x 8 o-groups), ~74KB
// ---------------------------------------------------------------------------
__global__ void __launch_bounds__(224) k3_main(
    const float* __restrict__ x,        // [B, C, HW]
    const float* __restrict__ conv2_w,  // [32]
    float* __restrict__ out_map,        // [B, HW]
    float* __restrict__ out_feat)       // [B, C, HW]
{
    extern __shared__ char sm3[];
    float2* A2    = (float2*)sm3;                          // [256*34] 69,632B
    float4* red4  = (float4*)(sm3 + CC * A_CSTR * 8);      // [224]
    float4* marr4 = (float4*)((char*)red4 + 224 * 16);     // [28]
    float*  w2s   = (float*)((char*)marr4 + 28 * 16);      // [32]

    int b    = blockIdx.y;
    int tile = blockIdx.x;
    int tid  = threadIdx.x;
    int og   = tid & 7;
    int ql   = tid >> 3;

    {   // pure copy of g_A[b] (LDG.128 -> STS.128)
        const ulonglong2* src = (const ulonglong2*)(g_A + (size_t)b * CC * A_CSTR);
        ulonglong2* dst = (ulonglong2*)A2;
        for (int i = tid; i < CC * A_CSTR / 2; i += 224) dst[i] = src[i];
    }
    if (tid < O1) w2s[tid] = conv2_w[tid];
    __syncthreads();

    int p = (tile * 28 + ql) * 4;            // 196 quads exactly
    const float* xb = x + (size_t)b * CC * HW;
    const ull_t* Au = (const ull_t*)A2;

    ull_t acc[4][2];
#pragma unroll
    for (int oo = 0; oo < 4; oo++) { acc[oo][0] = 0ull; acc[oo][1] = 0ull; }

#pragma unroll 4
    for (int c = 0; c < CC; c++) {
        ulonglong2 xv = *(const ulonglong2*)(xb + (size_t)c * HW + p);
        const ulonglong2* ap2 = (const ulonglong2*)(Au + c * A_CSTR + og * 4);
        ulonglong2 apA = ap2[0];   // {dup a[og*4+0], dup a[og*4+1]}
        ulonglong2 apB = ap2[1];   // {dup a[og*4+2], dup a[og*4+3]}
        acc[0][0] = fma2(apA.x, xv.x, acc[0][0]);
        acc[0][1] = fma2(apA.x, xv.y, acc[0][1]);
        acc[1][0] = fma2(apA.y, xv.x, acc[1][0]);
        acc[1][1] = fma2(apA.y, xv.y, acc[1][1]);
        acc[2][0] = fma2(apB.x, xv.x, acc[2][0]);
        acc[2][1] = fma2(apB.x, xv.y, acc[2][1]);
        acc[3][0] = fma2(apB.y, xv.x, acc[3][0]);
        acc[3][1] = fma2(apB.y, xv.y, acc[3][1]);
    }

    float4 ps = make_float4(0.f, 0.f, 0.f, 0.f);
#pragma unroll
    for (int oo = 0; oo < 4; oo++) {
        float w = w2s[og * 4 + oo];
        float2 lo = unpk2(acc[oo][0]);
        float2 hi = unpk2(acc[oo][1]);
        ps.x = fmaf(w, fmaxf(lo.x, 0.f), ps.x);
        ps.y = fmaf(w, fmaxf(lo.y, 0.f), ps.y);
        ps.z = fmaf(w, fmaxf(hi.x, 0.f), ps.z);
        ps.w = fmaf(w, fmaxf(hi.y, 0.f), ps.w);
    }
    red4[tid] = ps;
    __syncthreads();

    if (tid < 28) {
        float4 t = make_float4(0.f, 0.f, 0.f, 0.f);
#pragma unroll
        for (int g = 0; g < 8; g++) {
            float4 r = red4[tid * 8 + g];
            t.x += r.x; t.y += r.y; t.z += r.z; t.w += r.w;
        }
        float4 mm;
        mm.x = 1.f / (1.f + __expf(-t.x));
        mm.y = 1.f / (1.f + __expf(-t.y));
        mm.z = 1.f / (1.f + __expf(-t.z));
        mm.w = 1.f / (1.f + __expf(-t.w));
        marr4[tid] = mm;
        *(float4*)(out_map + b * HW + (tile * 28 + tid) * 4) = mm;
    }
    __syncthreads();

    {   // epilogue: feat = map * x
        int qq = tid % 28;
        int cg = tid / 28;
        int pp = (tile * 28 + qq) * 4;
        float4 mm = marr4[qq];
        float* fb = out_feat + (size_t)b * CC * HW;
        for (int c = cg; c < CC; c += 8) {
            float4 xv = *(const float4*)(xb + (size_t)c * HW + pp);
            float4 r;
            r.x = mm.x * xv.x; r.y = mm.y * xv.y;
            r.z = mm.z * xv.z; r.w = mm.w * xv.w;
            *(float4*)(fb + (size_t)c * HW + pp) = r;
        }
    }
}

// ---------------------------------------------------------------------------
extern "C" void kernel_launch(void* const* d_in, const int* in_sizes, int n_in,
                              void* d_out, int out_size)
{
    (void)in_sizes; (void)n_in; (void)out_size;
    const float* x        = (const float*)d_in[0];
    const float* attr_oh  = (const float*)d_in[1];
    const float* W_emb    = (const float*)d_in[2];
    const float* b_emb    = (const float*)d_in[3];
    const int*   h1       = (const int*)  d_in[4];
    const float* s1       = (const float*)d_in[5];
    const int*   h2       = (const int*)  d_in[6];
    const float* s2       = (const float*)d_in[7];
    const float* conv1_w  = (const float*)d_in[8];
    const float* conv2_w  = (const float*)d_in[9];

    float* out      = (float*)d_out;
    float* out_map  = out;               // [64,784]
    float* out_feat = out + BB * HW;     // [64,256,784]

    const int sh1  = (BB * ATTRN + 4 * ATTRN) * 4;           // ~81.6 KB
    const int sh2  = O1 * DDIM * 8 + 2 * DDIM * 8;           // ~68 KB
    const int sh2b = O1 * 257 * 4;                           // ~32.9 KB
    const int sh3  = CC * A_CSTR * 8 + 224 * 16 + 28 * 16 + O1 * 4;  // ~73.8 KB
    cudaFuncSetAttribute(k1_emb,     cudaFuncAttributeMaxDynamicSharedMemorySize, sh1);
    cudaFuncSetAttribute(k2_cm,      cudaFuncAttributeMaxDynamicSharedMemorySize, sh2);
    cudaFuncSetAttribute(k2b_gather, cudaFuncAttributeMaxDynamicSharedMemorySize, sh2b);
    cudaFuncSetAttribute(k3_main,    cudaFuncAttributeMaxDynamicSharedMemorySize, sh3);

    k1_emb<<<64, 256, sh1>>>(attr_oh, W_emb, b_emb, s1);
    k2_cm<<<dim3(8, 16), 256, sh2>>>(conv1_w, h1);
    k2b_gather<<<BB, 256, sh2b>>>(h2, s2);
    k3_main<<<dim3(7, BB), 224, sh3>>>(x, conv2_w, out_map, out_feat);
}